// round 6
// baseline (speedup 1.0000x reference)
#include <cuda_runtime.h>

#define NW 1440
#define NH 721
#define NK 24
#define NHW (NH*NW)

#define PI_D 3.14159265358979323846

__device__ float g_cos[NH];
__device__ float g_fcor[NH];
__device__ float g_bm[NK];
__device__ float g_db[NK];
__device__ float g_lr[NK];     // 287 * log(bm[k]/bm[k+1]), 0 at k=NK-1
__device__ float g_rbm[NK];
__device__ float g_cdip[NK];
__device__ float g_cb[NK + 1]; // b_if[k] - b_if[0]

__device__ __forceinline__ float bif_f(int k) {
    if (k >= NK) return 0.04f;
    double step = (0.04 - 1.0) / 24.0;
    return (float)(1.0 + step * (double)k);
}
__device__ __forceinline__ float bmid_f(int k) {
    return 0.5f * (bif_f(k) + bif_f(k + 1));
}

__global__ void hcbs_setup() {
    int i = blockIdx.x * blockDim.x + threadIdx.x;
    if (i < NH) {
        double colat = (double)i * (PI_D / 720.0);
        float lat = (float)(PI_D / 2.0 - colat);
        g_cos[i]  = fmaxf((float)cos((double)lat), 1e-3f);
        g_fcor[i] = (float)(2.0 * 7.292e-5) * (float)sin((double)lat);
    }
    if (i <= NK) g_cb[i] = bif_f(i) - 1.0f;
    if (i < NK) {
        float bm = bmid_f(i);
        g_bm[i]  = bm;
        g_db[i]  = bif_f(i + 1) - bif_f(i);
        g_rbm[i] = 1.0f / bm;
        int up = (i == 0) ? 1 : ((i == NK - 1) ? (NK - 1) : (i + 1));
        int dn = (i == 0) ? 0 : (i - 1);
        g_cdip[i] = 1.0f / (bmid_f(up) - bmid_f(dn));
        g_lr[i] = (i < NK - 1) ? (287.0f * logf(bm / bmid_f(i + 1))) : 0.0f;
    }
}

// block: 32 lon-points x 12 level-slices (each thread owns levels 2*ky, 2*ky+1)
__global__ void __launch_bounds__(384, 2)
hcbs_main(const float* __restrict__ uvp,
          const float* __restrict__ Tp,
          const float* __restrict__ qp,
          const float* __restrict__ psp,
          float* __restrict__ outp)
{
    __shared__ float4 sm_cen[NK * 32];      // (u,v,T,q) centers per level
    __shared__ float4 sm_scan[12 * 32];     // (t, lr*gTx, lr*gTy, -)

    const int lane = threadIdx.x;
    const int ky   = threadIdx.y;
    const int k0   = 2 * ky, k1 = k0 + 1;
    const int y    = blockIdx.y;
    const int x    = blockIdx.x * 32 + lane;
    const int idx  = y * NW + x;

    const int iW = (x == 0)      ? idx + (NW - 1) : idx - 1;
    const int iE = (x == NW - 1) ? idx - (NW - 1) : idx + 1;
    const int iN = (y == 0)      ? idx : idx - NW;
    const int iS = (y == NH - 1) ? idx : idx + NW;
    const bool edgeW = (lane == 0), edgeE = (lane == 31);
    const unsigned FULL = 0xffffffffu;

    const float DT   = (float)(PI_D / 720.0);
    const float hl   = 0.5f / DT;
    const float phs  = (y == 0 || y == NH - 1) ? (1.0f / DT) : (0.5f / DT);
    const float invR = 1.0f / 6371000.0f;
    const float cosc = g_cos[y];
    const float cosN = g_cos[(y == 0) ? 0 : (y - 1)];
    const float cosS = g_cos[(y == NH - 1) ? (NH - 1) : (y + 1)];
    const float fc   = g_fcor[y];
    const float iRc  = invR / cosc;
    const float hx   = hl * iRc;
    const float aN   = cosN * phs * iRc;
    const float aS   = cosS * phs * iRc;
    const float py   = phs * invR;

    float psC = psp[idx];
    float psNl = psp[iN], psSl = psp[iS];
    float psW = __shfl_up_sync(FULL, psC, 1);
    float psE = __shfl_down_sync(FULL, psC, 1);
    if (edgeW) psW = psp[iW];
    if (edgeE) psE = psp[iE];
    float gpsx = (psE - psW) * hx;
    float gpsy = -(psSl - psNl) * py;
    float ips  = 1.0f / psC;

    const float2* uv2 = (const float2*)uvp;

    float uc[2], vcv[2], Tc[2], qc[2];
    float divg[2], zeta[2], vg[2], tt[2];
    float gkx[2], gky[2], gTx[2], gTy[2], gqx[2], gqy[2];
    float lrv[2];

    #pragma unroll
    for (int j = 0; j < 2; j++) {
        const int k = k0 + j;
        const int b = k * NHW;
        float2 c = uv2[b + idx];
        float2 n = uv2[b + iN];
        float2 s = uv2[b + iS];
        float Tcv = Tp[b + idx], Tn = Tp[b + iN], Ts = Tp[b + iS];
        float qcv = qp[b + idx], qn = qp[b + iN], qs = qp[b + iS];

        float uw = __shfl_up_sync(FULL, c.x, 1);
        float vw = __shfl_up_sync(FULL, c.y, 1);
        float ue = __shfl_down_sync(FULL, c.x, 1);
        float ve = __shfl_down_sync(FULL, c.y, 1);
        float Tw = __shfl_up_sync(FULL, Tcv, 1);
        float Te = __shfl_down_sync(FULL, Tcv, 1);
        float qw = __shfl_up_sync(FULL, qcv, 1);
        float qe = __shfl_down_sync(FULL, qcv, 1);
        if (edgeW) {
            float2 t2 = uv2[b + iW];
            uw = t2.x; vw = t2.y; Tw = Tp[b + iW]; qw = qp[b + iW];
        }
        if (edgeE) {
            float2 t2 = uv2[b + iE];
            ue = t2.x; ve = t2.y; Te = Tp[b + iE]; qe = qp[b + iE];
        }

        divg[j] = (ue - uw) * hx - (s.y * aS - n.y * aN);
        zeta[j] = (ve - vw) * hx + (s.x * aS - n.x * aN);

        float keW = 0.5f * (uw * uw + vw * vw);
        float keE = 0.5f * (ue * ue + ve * ve);
        float keN = 0.5f * (n.x * n.x + n.y * n.y);
        float keS = 0.5f * (s.x * s.x + s.y * s.y);
        gkx[j] = (keE - keW) * hx;
        gky[j] = -(keS - keN) * py;
        gTx[j] = (Te - Tw) * hx;
        gTy[j] = -(Ts - Tn) * py;
        gqx[j] = (qe - qw) * hx;
        gqy[j] = -(qs - qn) * py;

        vg[j] = c.x * gpsx + c.y * gpsy;
        tt[j] = g_db[k] * (psC * divg[j] + vg[j]);
        lrv[j] = g_lr[k];

        uc[j] = c.x; vcv[j] = c.y; Tc[j] = Tcv; qc[j] = qcv;
        sm_cen[k * 32 + lane] = make_float4(c.x, c.y, Tcv, qcv);
    }

    // ---- block scan over level-pairs (Hillis-Steele, 12 elements) ----
    float4 v = make_float4(tt[0] + tt[1],
                           lrv[0] * gTx[0] + lrv[1] * gTx[1],
                           lrv[0] * gTy[0] + lrv[1] * gTy[1], 0.0f);
    sm_scan[ky * 32 + lane] = v;
    #pragma unroll
    for (int s = 1; s < 12; s <<= 1) {
        __syncthreads();
        float4 part = make_float4(0.f, 0.f, 0.f, 0.f);
        if (ky >= s) part = sm_scan[(ky - s) * 32 + lane];
        __syncthreads();
        v.x += part.x; v.y += part.y; v.z += part.z;
        sm_scan[ky * 32 + lane] = v;
    }
    __syncthreads();
    float4 tot  = sm_scan[11 * 32 + lane];
    float4 prev = make_float4(0.f, 0.f, 0.f, 0.f);
    if (ky > 0) prev = sm_scan[(ky - 1) * 32 + lane];

    float dps = -tot.x;
    if (ky == 0) outp[(size_t)4 * NK * NHW + idx] = dps;

    // vertical neighbor centers
    float4 own0 = make_float4(uc[0], vcv[0], Tc[0], qc[0]);
    float4 own1 = make_float4(uc[1], vcv[1], Tc[1], qc[1]);
    float4 dn0 = (k0 > 0)      ? sm_cen[(k0 - 1) * 32 + lane] : own0;
    float4 up1 = (k1 < NK - 1) ? sm_cen[(k1 + 1) * 32 + lane] : own1;

    // cumulative quantities per level
    float s1k0 = prev.x + tt[0];
    float s1k1 = v.x;
    float gpxA = prev.y,               gpyA = prev.z;
    float gpxB = prev.y + lrv[0] * gTx[0], gpyB = prev.z + lrv[0] * gTy[0];

    float ChLo0 = -(((k0 > 0) ? prev.x : 0.0f) + g_cb[k0] * dps);
    if (k0 == 0) ChLo0 = 0.0f;
    float ChHi0 = -(s1k0 + g_cb[k1] * dps);
    float ChHi1 = -(s1k1 + g_cb[k1 + 1] * dps);

    const float RCP = 287.0f / 1004.0f;

    float2* o_duv2 = (float2*)outp;
    float*  o_dT   = outp + (size_t)2 * NK * NHW;
    float*  o_dq   = outp + (size_t)3 * NK * NHW;

    #pragma unroll
    for (int j = 0; j < 2; j++) {
        const int k = k0 + j;
        const int b = k * NHW;
        float Cm = (j == 0) ? 0.5f * (ChLo0 + ChHi0) : 0.5f * (ChHi0 + ChHi1);
        float om = g_bm[k] * (dps + vg[j]) + Cm;

        float4 up = (j == 0) ? own1 : up1;
        float4 dn = (j == 0) ? dn0  : own0;
        float cd = g_cdip[k] * ips;
        float ddpu = (up.x - dn.x) * cd;
        float ddpv = (up.y - dn.y) * cd;
        float ddpT = (up.z - dn.z) * cd;
        float ddpq = (up.w - dn.w) * cd;

        float av  = zeta[j] + fc;
        float pgf = 287.0f * Tc[j] * ips;
        float gpxv = (j == 0) ? gpxA : gpxB;
        float gpyv = (j == 0) ? gpyA : gpyB;

        float du =  av * vcv[j] - (gkx[j] + gpxv) - pgf * gpsx - Cm * ddpu;
        float dv = -av * uc[j]  - (gky[j] + gpyv) - pgf * gpsy - Cm * ddpv;
        float dT = -(uc[j] * gTx[j] + vcv[j] * gTy[j]) - Cm * ddpT
                   + RCP * Tc[j] * om * (ips * g_rbm[k]);
        float dq = -(uc[j] * gqx[j] + vcv[j] * gqy[j]) - Cm * ddpq;

        o_duv2[b + idx] = make_float2(du, dv);
        o_dT[b + idx]   = dT;
        o_dq[b + idx]   = dq;
    }
}

extern "C" void kernel_launch(void* const* d_in, const int* in_sizes, int n_in,
                              void* d_out, int out_size) {
    const float* uv = nullptr;
    const float* T  = nullptr;
    const float* q  = nullptr;
    const float* ps = nullptr;
    for (int i = 0; i < n_in; i++) {
        long long sz = in_sizes[i];
        if (sz == 2LL * NK * NHW)      uv = (const float*)d_in[i];
        else if (sz == (long long)NHW) ps = (const float*)d_in[i];
        else if (sz == (long long)NK * NHW) {
            if (!T) T = (const float*)d_in[i];
            else    q = (const float*)d_in[i];
        }
    }
    hcbs_setup<<<6, 128>>>();
    dim3 grid(NW / 32, NH);
    dim3 block(32, 12);
    hcbs_main<<<grid, block>>>(uv, T, q, ps, (float*)d_out);
}

// round 8
// speedup vs baseline: 1.4494x; 1.4494x over previous
#include <cuda_runtime.h>

#define NW 1440
#define NH 721
#define NK 24
#define NHW (NH*NW)
#define NP (NHW/2)
#define NPR (NW/2)

#define PI_D 3.14159265358979323846

__device__ float g_cos[NH];
__device__ float g_fcor[NH];
__device__ float g_bm[NK];
__device__ float g_db[NK];
__device__ float g_lr[NK];    // 287 * log(bm[k]/bm[k+1])
__device__ float g_rbm[NK];
__device__ float g_cdip[NK];

__device__ __forceinline__ float bif_f(int k) {
    if (k >= NK) return 0.04f;
    double step = (0.04 - 1.0) / 24.0;
    return (float)(1.0 + step * (double)k);
}
__device__ __forceinline__ float bmid_f(int k) {
    return 0.5f * (bif_f(k) + bif_f(k + 1));
}

__global__ void hcbs_setup() {
    int i = blockIdx.x * blockDim.x + threadIdx.x;
    if (i < NH) {
        double colat = (double)i * (PI_D / 720.0);
        float lat = (float)(PI_D / 2.0 - colat);
        g_cos[i]  = fmaxf((float)cos((double)lat), 1e-3f);
        g_fcor[i] = (float)(2.0 * 7.292e-5) * (float)sin((double)lat);
    }
    if (i < NK) {
        float bm = bmid_f(i);
        g_bm[i]  = bm;
        g_db[i]  = bif_f(i + 1) - bif_f(i);
        g_rbm[i] = 1.0f / bm;
        int up = (i == 0) ? 1 : ((i == NK - 1) ? (NK - 1) : (i + 1));
        int dn = (i == 0) ? 0 : (i - 1);
        g_cdip[i] = 1.0f / (bmid_f(up) - bmid_f(dn));
        g_lr[i] = (i < NK - 1) ? (287.0f * logf(bm / bmid_f(i + 1))) : 0.0f;
    }
}

struct Neigh {
    float4 n4, s4;
    float2 w2, e2, TN, TS, qN, qS;
    float  TW, TE, qW, qE;
};

__global__ void __launch_bounds__(128, 4)
hcbs_main(const float* __restrict__ uvp,
          const float* __restrict__ Tp,
          const float* __restrict__ qp,
          const float* __restrict__ psp,
          float* __restrict__ outp)
{
    int p = blockIdx.x * blockDim.x + threadIdx.x;
    if (p >= NP) return;
    int y  = p / NPR;
    int xp = p - y * NPR;
    int x0 = 2 * xp;
    int idx0 = 2 * p;

    const int iW = (x0 == 0)      ? idx0 + (NW - 1) : idx0 - 1;
    const int iE = (x0 == NW - 2) ? idx0 + 2 - NW   : idx0 + 2;
    const int pN = (y == 0)       ? p : p - NPR;
    const int pS = (y == NH - 1)  ? p : p + NPR;

    const float4* uv4 = (const float4*)uvp;
    const float2* uv2 = (const float2*)uvp;
    const float2* T2  = (const float2*)Tp;
    const float2* q2  = (const float2*)qp;
    const float2* ps2 = (const float2*)psp;

    float4* o_duv4 = (float4*)outp;
    float2* o_dT2  = (float2*)(outp + (size_t)2 * NK * NHW);
    float2* o_dq2  = (float2*)(outp + (size_t)3 * NK * NHW);
    float2* o_dps2 = (float2*)(outp + (size_t)4 * NK * NHW);

    const float DT   = (float)(PI_D / 720.0);
    const float hl   = 0.5f / DT;
    const float phs  = (y == 0 || y == NH - 1) ? (1.0f / DT) : (0.5f / DT);
    const float invR = 1.0f / 6371000.0f;

    const float cosc = g_cos[y];
    const float cosN = g_cos[(y == 0) ? 0 : (y - 1)];
    const float cosS = g_cos[(y == NH - 1) ? (NH - 1) : (y + 1)];
    const float fc   = g_fcor[y];
    const float iRc  = invR / cosc;
    const float hx   = hl * iRc;
    const float aN   = cosN * phs * iRc;
    const float aS   = cosS * phs * iRc;
    const float py   = phs * invR;

    float2 psC = ps2[p];
    float2 psN = ps2[pN], psS = ps2[pS];
    float psW = psp[iW], psE = psp[iE];

    float gpsx0 = (psC.y - psW) * hx;
    float gpsx1 = (psE - psC.x) * hx;
    float gpsy0 = -(psS.x - psN.x) * py;
    float gpsy1 = -(psS.y - psN.y) * py;
    float ips0 = 1.0f / psC.x, ips1 = 1.0f / psC.y;

    // ---------------- sweep 1: dps/dt ----------------
    float dps0 = 0.0f, dps1 = 0.0f;
    #pragma unroll 4
    for (int k = 0; k < NK; k++) {
        int b4 = k * NP + p;
        int b2 = k * NHW;
        float4 c  = uv4[b4];
        float4 n4 = uv4[k * NP + pN];
        float4 s4 = uv4[k * NP + pS];
        float uW = uv2[b2 + iW].x;
        float uE = uv2[b2 + iE].x;
        float divg0 = (c.z - uW) * hx - (s4.y * aS - n4.y * aN);
        float divg1 = (uE - c.x) * hx - (s4.w * aS - n4.w * aN);
        float vg0 = c.x * gpsx0 + c.y * gpsy0;
        float vg1 = c.z * gpsx1 + c.w * gpsy1;
        float db = g_db[k];
        dps0 -= db * (psC.x * divg0 + vg0);
        dps1 -= db * (psC.y * divg1 + vg1);
    }
    o_dps2[p] = make_float2(dps0, dps1);

    // ---------------- sweep 2: software-pipelined level sweep ----------------
    float Ch0 = 0.0f, Ch1 = 0.0f;
    float gpx0 = 0.0f, gpy0 = 0.0f, gpx1 = 0.0f, gpy1 = 0.0f;
    float4 cU = uv4[p];
    float2 cT = T2[p], cQ = q2[p];
    float4 pU = cU;
    float2 pT = cT, pQ = cQ;
    const float RCP = 287.0f / 1004.0f;

    // prefetch neighbors for k=0
    Neigh A;
    {
        A.n4 = uv4[pN]; A.s4 = uv4[pS];
        A.w2 = uv2[iW]; A.e2 = uv2[iE];
        A.TN = T2[pN];  A.TS = T2[pS];
        A.TW = Tp[iW];  A.TE = Tp[iE];
        A.qN = q2[pN];  A.qS = q2[pS];
        A.qW = qp[iW];  A.qE = qp[iE];
    }

    #pragma unroll 2
    for (int k = 0; k < NK; k++) {
        int b4 = k * NP;
        int ku = (k + 1 < NK) ? (k + 1) : k;
        int n4b = ku * NP;
        int n2b = ku * NHW;

        // issue next-level loads first (center rotation + neighbors)
        float4 uU = uv4[n4b + p];
        float2 uT = T2[n4b + p];
        float2 uQ = q2[n4b + p];
        Neigh B;
        B.n4 = uv4[n4b + pN]; B.s4 = uv4[n4b + pS];
        B.w2 = uv2[n2b + iW]; B.e2 = uv2[n2b + iE];
        B.TN = T2[n4b + pN];  B.TS = T2[n4b + pS];
        B.TW = Tp[n2b + iW];  B.TE = Tp[n2b + iE];
        B.qN = q2[n4b + pN];  B.qS = q2[n4b + pS];
        B.qW = qp[n2b + iW];  B.qE = qp[n2b + iE];

        float bm = g_bm[k], db = g_db[k];

        float zeta0 = (cU.w - A.w2.y) * hx + (A.s4.x * aS - A.n4.x * aN);
        float divg0 = (cU.z - A.w2.x) * hx - (A.s4.y * aS - A.n4.y * aN);
        float zeta1 = (A.e2.y - cU.y) * hx + (A.s4.z * aS - A.n4.z * aN);
        float divg1 = (A.e2.x - cU.x) * hx - (A.s4.w * aS - A.n4.w * aN);

        float keW  = 0.5f * (A.w2.x * A.w2.x + A.w2.y * A.w2.y);
        float keE  = 0.5f * (A.e2.x * A.e2.x + A.e2.y * A.e2.y);
        float ke0  = 0.5f * (cU.x * cU.x + cU.y * cU.y);
        float ke1  = 0.5f * (cU.z * cU.z + cU.w * cU.w);
        float keN0 = 0.5f * (A.n4.x * A.n4.x + A.n4.y * A.n4.y);
        float keN1 = 0.5f * (A.n4.z * A.n4.z + A.n4.w * A.n4.w);
        float keS0 = 0.5f * (A.s4.x * A.s4.x + A.s4.y * A.s4.y);
        float keS1 = 0.5f * (A.s4.z * A.s4.z + A.s4.w * A.s4.w);

        float gkx0 = (ke1 - keW) * hx,  gkx1 = (keE - ke0) * hx;
        float gky0 = -(keS0 - keN0) * py, gky1 = -(keS1 - keN1) * py;
        float gTx0 = (cT.y - A.TW) * hx, gTx1 = (A.TE - cT.x) * hx;
        float gTy0 = -(A.TS.x - A.TN.x) * py, gTy1 = -(A.TS.y - A.TN.y) * py;
        float gqx0 = (cQ.y - A.qW) * hx, gqx1 = (A.qE - cQ.x) * hx;
        float gqy0 = -(A.qS.x - A.qN.x) * py, gqy1 = -(A.qS.y - A.qN.y) * py;

        float vg0 = cU.x * gpsx0 + cU.y * gpsy0;
        float vg1 = cU.z * gpsx1 + cU.w * gpsy1;
        float Cn0 = Ch0 - (db * (dps0 + psC.x * divg0 + vg0));
        float Cn1 = Ch1 - (db * (dps1 + psC.y * divg1 + vg1));
        float Cm0 = 0.5f * (Ch0 + Cn0);
        float Cm1 = 0.5f * (Ch1 + Cn1);
        float om0 = bm * (dps0 + vg0) + Cm0;
        float om1 = bm * (dps1 + vg1) + Cm1;

        float cd0 = g_cdip[k] * ips0;
        float cd1 = g_cdip[k] * ips1;
        float ddpu0 = (uU.x - pU.x) * cd0, ddpv0 = (uU.y - pU.y) * cd0;
        float ddpu1 = (uU.z - pU.z) * cd1, ddpv1 = (uU.w - pU.w) * cd1;
        float ddpT0 = (uT.x - pT.x) * cd0, ddpT1 = (uT.y - pT.y) * cd1;
        float ddpq0 = (uQ.x - pQ.x) * cd0, ddpq1 = (uQ.y - pQ.y) * cd1;

        float av0 = zeta0 + fc, av1 = zeta1 + fc;
        float pgf0 = 287.0f * cT.x * ips0;
        float pgf1 = 287.0f * cT.y * ips1;
        float orb = g_rbm[k];

        float du0 =  av0 * cU.y - (gkx0 + gpx0) - pgf0 * gpsx0 - Cm0 * ddpu0;
        float dv0 = -av0 * cU.x - (gky0 + gpy0) - pgf0 * gpsy0 - Cm0 * ddpv0;
        float du1 =  av1 * cU.w - (gkx1 + gpx1) - pgf1 * gpsx1 - Cm1 * ddpu1;
        float dv1 = -av1 * cU.z - (gky1 + gpy1) - pgf1 * gpsy1 - Cm1 * ddpv1;
        float dT0 = -(cU.x * gTx0 + cU.y * gTy0) - Cm0 * ddpT0
                    + RCP * cT.x * om0 * (ips0 * orb);
        float dT1 = -(cU.z * gTx1 + cU.w * gTy1) - Cm1 * ddpT1
                    + RCP * cT.y * om1 * (ips1 * orb);
        float dq0 = -(cU.x * gqx0 + cU.y * gqy0) - Cm0 * ddpq0;
        float dq1 = -(cU.z * gqx1 + cU.w * gqy1) - Cm1 * ddpq1;

        o_duv4[b4 + p] = make_float4(du0, dv0, du1, dv1);
        o_dT2[b4 + p]  = make_float2(dT0, dT1);
        o_dq2[b4 + p]  = make_float2(dq0, dq1);

        float lrr = g_lr[k];
        gpx0 += lrr * gTx0; gpy0 += lrr * gTy0;
        gpx1 += lrr * gTx1; gpy1 += lrr * gTy1;

        Ch0 = Cn0; Ch1 = Cn1;
        pU = cU; pT = cT; pQ = cQ;
        cU = uU; cT = uT; cQ = uQ;
        A = B;
    }
}

extern "C" void kernel_launch(void* const* d_in, const int* in_sizes, int n_in,
                              void* d_out, int out_size) {
    const float* uv = nullptr;
    const float* T  = nullptr;
    const float* q  = nullptr;
    const float* ps = nullptr;
    for (int i = 0; i < n_in; i++) {
        long long sz = in_sizes[i];
        if (sz == 2LL * NK * NHW)      uv = (const float*)d_in[i];
        else if (sz == (long long)NHW) ps = (const float*)d_in[i];
        else if (sz == (long long)NK * NHW) {
            if (!T) T = (const float*)d_in[i];
            else    q = (const float*)d_in[i];
        }
    }
    hcbs_setup<<<6, 128>>>();
    int threads = 128;
    int blocks  = (NP + threads - 1) / threads;
    hcbs_main<<<blocks, threads>>>(uv, T, q, ps, (float*)d_out);
}

// round 9
// speedup vs baseline: 1.5918x; 1.0983x over previous
#include <cuda_runtime.h>

#define NW 1440
#define NH 721
#define NK 24
#define NHW (NH*NW)
#define NP (NHW/2)
#define NPR (NW/2)

#define PI_D 3.14159265358979323846

__device__ float g_cos[NH];
__device__ float g_fcor[NH];
__device__ float g_bm[NK];
__device__ float g_db[NK];
__device__ float g_lr[NK];    // 287 * log(bm[k]/bm[k+1])
__device__ float g_rbm[NK];
__device__ float g_cdip[NK];

__device__ __forceinline__ float bif_f(int k) {
    if (k >= NK) return 0.04f;
    double step = (0.04 - 1.0) / 24.0;
    return (float)(1.0 + step * (double)k);
}
__device__ __forceinline__ float bmid_f(int k) {
    return 0.5f * (bif_f(k) + bif_f(k + 1));
}

__global__ void hcbs_setup() {
    int i = blockIdx.x * blockDim.x + threadIdx.x;
    if (i < NH) {
        double colat = (double)i * (PI_D / 720.0);
        float lat = (float)(PI_D / 2.0 - colat);
        g_cos[i]  = fmaxf((float)cos((double)lat), 1e-3f);
        g_fcor[i] = (float)(2.0 * 7.292e-5) * (float)sin((double)lat);
    }
    if (i < NK) {
        float bm = bmid_f(i);
        g_bm[i]  = bm;
        g_db[i]  = bif_f(i + 1) - bif_f(i);
        g_rbm[i] = 1.0f / bm;
        int up = (i == 0) ? 1 : ((i == NK - 1) ? (NK - 1) : (i + 1));
        int dn = (i == 0) ? 0 : (i - 1);
        g_cdip[i] = 1.0f / (bmid_f(up) - bmid_f(dn));
        g_lr[i] = (i < NK - 1) ? (287.0f * logf(bm / bmid_f(i + 1))) : 0.0f;
    }
}

__global__ void __launch_bounds__(128, 6)
hcbs_main(const float* __restrict__ uvp,
          const float* __restrict__ Tp,
          const float* __restrict__ qp,
          const float* __restrict__ psp,
          float* __restrict__ outp)
{
    int p = blockIdx.x * blockDim.x + threadIdx.x;
    if (p >= NP) return;
    int y  = p / NPR;
    int xp = p - y * NPR;
    int x0 = 2 * xp;
    int idx0 = 2 * p;

    const int iW = (x0 == 0)      ? idx0 + (NW - 1) : idx0 - 1;
    const int iE = (x0 == NW - 2) ? idx0 + 2 - NW   : idx0 + 2;
    const int pN = (y == 0)       ? p : p - NPR;
    const int pS = (y == NH - 1)  ? p : p + NPR;

    const float4* uv4 = (const float4*)uvp;
    const float2* uv2 = (const float2*)uvp;
    const float2* T2  = (const float2*)Tp;
    const float2* q2  = (const float2*)qp;
    const float2* ps2 = (const float2*)psp;

    float4* o_duv4 = (float4*)outp;
    float2* o_dT2  = (float2*)(outp + (size_t)2 * NK * NHW);
    float2* o_dq2  = (float2*)(outp + (size_t)3 * NK * NHW);
    float2* o_dps2 = (float2*)(outp + (size_t)4 * NK * NHW);

    const float DT   = (float)(PI_D / 720.0);
    const float hl   = 0.5f / DT;
    const float phs  = (y == 0 || y == NH - 1) ? (1.0f / DT) : (0.5f / DT);
    const float invR = 1.0f / 6371000.0f;

    const float cosc = g_cos[y];
    const float cosN = g_cos[(y == 0) ? 0 : (y - 1)];
    const float cosS = g_cos[(y == NH - 1) ? (NH - 1) : (y + 1)];
    const float fc   = g_fcor[y];
    const float iRc  = invR / cosc;
    const float hx   = hl * iRc;
    const float aN   = cosN * phs * iRc;
    const float aS   = cosS * phs * iRc;
    const float py   = phs * invR;

    float2 psC = ps2[p];
    float2 psN = ps2[pN], psS = ps2[pS];
    float psW = psp[iW], psE = psp[iE];

    float gpsx0 = (psC.y - psW) * hx;
    float gpsx1 = (psE - psC.x) * hx;
    float gpsy0 = -(psS.x - psN.x) * py;
    float gpsy1 = -(psS.y - psN.y) * py;
    float ips0 = 1.0f / psC.x, ips1 = 1.0f / psC.y;

    // ---------------- sweep 1: dps/dt ----------------
    float dps0 = 0.0f, dps1 = 0.0f;
    #pragma unroll 4
    for (int k = 0; k < NK; k++) {
        int b4 = k * NP + p;
        int b2 = k * NHW;
        float4 c  = uv4[b4];
        float4 n4 = uv4[k * NP + pN];
        float4 s4 = uv4[k * NP + pS];
        float uW = uv2[b2 + iW].x;
        float uE = uv2[b2 + iE].x;
        float divg0 = (c.z - uW) * hx - (s4.y * aS - n4.y * aN);
        float divg1 = (uE - c.x) * hx - (s4.w * aS - n4.w * aN);
        float vg0 = c.x * gpsx0 + c.y * gpsy0;
        float vg1 = c.z * gpsx1 + c.w * gpsy1;
        float db = g_db[k];
        dps0 -= db * (psC.x * divg0 + vg0);
        dps1 -= db * (psC.y * divg1 + vg1);
    }
    o_dps2[p] = make_float2(dps0, dps1);

    // ---------------- sweep 2: level tendencies ----------------
    float Ch0 = 0.0f, Ch1 = 0.0f;
    float gpx0 = 0.0f, gpy0 = 0.0f, gpx1 = 0.0f, gpy1 = 0.0f;
    float4 cU = uv4[p];
    float2 cT = T2[p], cQ = q2[p];
    float4 pU = cU;
    float2 pT = cT, pQ = cQ;
    const float RCP = 287.0f / 1004.0f;

    #pragma unroll 1
    for (int k = 0; k < NK; k++) {
        int b4 = k * NP;
        int b2 = k * NHW;
        int ku = (k + 1 < NK) ? (k + 1) : k;

        float4 n4 = uv4[b4 + pN];
        float4 s4 = uv4[b4 + pS];
        float2 w2 = uv2[b2 + iW];
        float2 e2 = uv2[b2 + iE];
        float2 TN = T2[b4 + pN], TS = T2[b4 + pS];
        float  TW = Tp[b2 + iW], TE = Tp[b2 + iE];
        float2 qN = q2[b4 + pN], qS = q2[b4 + pS];
        float  qW = qp[b2 + iW], qE = qp[b2 + iE];
        float4 uU = uv4[ku * NP + p];
        float2 uT = T2[ku * NP + p];
        float2 uQ = q2[ku * NP + p];

        float bm = g_bm[k], db = g_db[k];

        float zeta0 = (cU.w - w2.y) * hx + (s4.x * aS - n4.x * aN);
        float divg0 = (cU.z - w2.x) * hx - (s4.y * aS - n4.y * aN);
        float zeta1 = (e2.y - cU.y) * hx + (s4.z * aS - n4.z * aN);
        float divg1 = (e2.x - cU.x) * hx - (s4.w * aS - n4.w * aN);

        float keW  = 0.5f * (w2.x * w2.x + w2.y * w2.y);
        float keE  = 0.5f * (e2.x * e2.x + e2.y * e2.y);
        float ke0  = 0.5f * (cU.x * cU.x + cU.y * cU.y);
        float ke1  = 0.5f * (cU.z * cU.z + cU.w * cU.w);
        float keN0 = 0.5f * (n4.x * n4.x + n4.y * n4.y);
        float keN1 = 0.5f * (n4.z * n4.z + n4.w * n4.w);
        float keS0 = 0.5f * (s4.x * s4.x + s4.y * s4.y);
        float keS1 = 0.5f * (s4.z * s4.z + s4.w * s4.w);

        float gkx0 = (ke1 - keW) * hx, gkx1 = (keE - ke0) * hx;
        float gky0 = -(keS0 - keN0) * py, gky1 = -(keS1 - keN1) * py;
        float gTx0 = (cT.y - TW) * hx, gTx1 = (TE - cT.x) * hx;
        float gTy0 = -(TS.x - TN.x) * py, gTy1 = -(TS.y - TN.y) * py;
        float gqx0 = (cQ.y - qW) * hx, gqx1 = (qE - cQ.x) * hx;
        float gqy0 = -(qS.x - qN.x) * py, gqy1 = -(qS.y - qN.y) * py;

        float vg0 = cU.x * gpsx0 + cU.y * gpsy0;
        float vg1 = cU.z * gpsx1 + cU.w * gpsy1;
        float Cn0 = Ch0 - (db * (dps0 + psC.x * divg0 + vg0));
        float Cn1 = Ch1 - (db * (dps1 + psC.y * divg1 + vg1));
        float Cm0 = 0.5f * (Ch0 + Cn0);
        float Cm1 = 0.5f * (Ch1 + Cn1);
        float om0 = bm * (dps0 + vg0) + Cm0;
        float om1 = bm * (dps1 + vg1) + Cm1;

        float cd0 = g_cdip[k] * ips0;
        float cd1 = g_cdip[k] * ips1;
        float ddpu0 = (uU.x - pU.x) * cd0, ddpv0 = (uU.y - pU.y) * cd0;
        float ddpu1 = (uU.z - pU.z) * cd1, ddpv1 = (uU.w - pU.w) * cd1;
        float ddpT0 = (uT.x - pT.x) * cd0, ddpT1 = (uT.y - pT.y) * cd1;
        float ddpq0 = (uQ.x - pQ.x) * cd0, ddpq1 = (uQ.y - pQ.y) * cd1;

        float av0 = zeta0 + fc, av1 = zeta1 + fc;
        float pgf0 = 287.0f * cT.x * ips0;
        float pgf1 = 287.0f * cT.y * ips1;
        float orb = g_rbm[k];

        float du0 =  av0 * cU.y - (gkx0 + gpx0) - pgf0 * gpsx0 - Cm0 * ddpu0;
        float dv0 = -av0 * cU.x - (gky0 + gpy0) - pgf0 * gpsy0 - Cm0 * ddpv0;
        float du1 =  av1 * cU.w - (gkx1 + gpx1) - pgf1 * gpsx1 - Cm1 * ddpu1;
        float dv1 = -av1 * cU.z - (gky1 + gpy1) - pgf1 * gpsy1 - Cm1 * ddpv1;
        float dT0 = -(cU.x * gTx0 + cU.y * gTy0) - Cm0 * ddpT0
                    + RCP * cT.x * om0 * (ips0 * orb);
        float dT1 = -(cU.z * gTx1 + cU.w * gTy1) - Cm1 * ddpT1
                    + RCP * cT.y * om1 * (ips1 * orb);
        float dq0 = -(cU.x * gqx0 + cU.y * gqy0) - Cm0 * ddpq0;
        float dq1 = -(cU.z * gqx1 + cU.w * gqy1) - Cm1 * ddpq1;

        o_duv4[b4 + p] = make_float4(du0, dv0, du1, dv1);
        o_dT2[b4 + p]  = make_float2(dT0, dT1);
        o_dq2[b4 + p]  = make_float2(dq0, dq1);

        float lrr = g_lr[k];
        gpx0 += lrr * gTx0; gpy0 += lrr * gTy0;
        gpx1 += lrr * gTx1; gpy1 += lrr * gTy1;

        Ch0 = Cn0; Ch1 = Cn1;
        pU = cU; pT = cT; pQ = cQ;
        cU = uU; cT = uT; cQ = uQ;
    }
}

extern "C" void kernel_launch(void* const* d_in, const int* in_sizes, int n_in,
                              void* d_out, int out_size) {
    const float* uv = nullptr;
    const float* T  = nullptr;
    const float* q  = nullptr;
    const float* ps = nullptr;
    for (int i = 0; i < n_in; i++) {
        long long sz = in_sizes[i];
        if (sz == 2LL * NK * NHW)      uv = (const float*)d_in[i];
        else if (sz == (long long)NHW) ps = (const float*)d_in[i];
        else if (sz == (long long)NK * NHW) {
            if (!T) T = (const float*)d_in[i];
            else    q = (const float*)d_in[i];
        }
    }
    hcbs_setup<<<6, 128>>>();
    int threads = 128;
    int blocks  = (NP + threads - 1) / threads;
    hcbs_main<<<blocks, threads>>>(uv, T, q, ps, (float*)d_out);
}